// round 7
// baseline (speedup 1.0000x reference)
#include <cuda_runtime.h>

#define GX 1024
#define GY 1024
#define GZ 40
#define MAXV 60000
#define MAXP 32
#define SLOTS (MAXV * MAXP)
#define BLK 256
#define IPT 4
#define TILE (BLK * IPT)
#define NMAX 1250000
#define NTMAX ((NMAX + TILE - 1) / TILE + 8)
#define PV_RESOLVED 0x40000000

// L2-resident open-addressing hash table. Entry (64-bit):
//   0 = empty; else ((flat+1) << 21) | key, key = n - i (n < 2^21).
// Slot ownership claimed once by CAS(0->entry); contenders for the same flat
// share identical high bits, so atomicMax on the packed word == per-voxel
// first-point claim. A flat occupies exactly ONE slot (probe order is
// deterministic; CAS only succeeds on 0).
#define HBITS 21
#define HSIZE (1u << HBITS)
#define HMASK (HSIZE - 1u)

__device__ __align__(16) unsigned long long g_htab[HSIZE];  // stream-zeroed by kD
__device__ int      g_sidx[NMAX];     // resolved hash-slot per point, -1 invalid
__device__ int      g_pvid[NMAX];     // reps only: PV_RESOLVED | vid (stale elsewhere, never read)
__device__ unsigned long long g_nrList[NMAX];  // non-reps: (i << 21) | i_rep
__device__ int      g_nrCount;        // reset by kD
__device__ unsigned g_status[NTMAX];  // lookback: 0 | 0x4000_0000|agg | 0x8000_0000|incl
__device__ int      g_voxelNum;
__device__ unsigned g_slots[SLOTS];   // 0 empty, else key = n - point_idx (reset by kD)
__device__ int      g_cnt[MAXV];      // reset by kD
__device__ int      g_coors[MAXV * 3];

__device__ __forceinline__ unsigned hslot(int flat) {
    return (unsigned)(((unsigned long long)(unsigned)flat * 0x9E3779B97F4A7C15ull) >> (64 - HBITS));
}

// ---------------------------------------------------------------------------
// A: coords -> hash claim; cache the resolved slot index per point.
// ---------------------------------------------------------------------------
__global__ void kA_claim(const float4* __restrict__ pts, int n) {
    int base = blockIdx.x * TILE;
    #pragma unroll
    for (int k = 0; k < IPT; k++) {
        int i = base + k * BLK + threadIdx.x;
        if (i >= n) break;
        float4 p = pts[i];
        // exact mirror of reference f32 math: floor((p - rmin) / vs)
        int cx = (int)floorf((p.x - (-51.2f)) / 0.1f);
        int cy = (int)floorf((p.y - (-51.2f)) / 0.1f);
        int cz = (int)floorf((p.z - (-5.0f)) / 0.2f);
        int sidx = -1;
        if ((unsigned)cx < GX && (unsigned)cy < GY && (unsigned)cz < GZ) {
            int flat = (cx * GY + cy) * GZ + cz;
            unsigned long long fp1 = (unsigned long long)(unsigned)(flat + 1);
            unsigned long long ent = (fp1 << 21) | (unsigned)(n - i);
            unsigned s = hslot(flat);
            for (;;) {
                unsigned long long cur = __ldcg(&g_htab[s]);
                if ((cur >> 21) == fp1) { atomicMax(&g_htab[s], ent); break; }
                if (cur == 0ull) {
                    unsigned long long old = atomicCAS(&g_htab[s], 0ull, ent);
                    if (old == 0ull) break;                                   // claimed
                    if ((old >> 21) == fp1) { atomicMax(&g_htab[s], ent); break; }
                }
                s = (s + 1) & HMASK;
            }
            sidx = (int)s;
        }
        g_sidx[i] = sidx;
    }
}

// ---------------------------------------------------------------------------
// B: one entry gather per point -> rep flags -> decoupled-lookback scan ->
// vid. Reps: write pvid, coors, slot0 + cnt (one rep per voxel: plain
// stores). Non-reps (~1% of points): warp-aggregated append to compact list.
// ---------------------------------------------------------------------------
__global__ void kB_scan_assign(int n, int nTiles) {
    const int tid = threadIdx.x;
    const int lane = tid & 31, wid = tid >> 5;
    const int tile = blockIdx.x;
    const int base = tile * TILE;

    __shared__ int s_warp[BLK / 32];
    __shared__ int s_wexcl[BLK / 32];
    __shared__ int s_run;
    __shared__ int s_excl;

    if (tid == 0) s_run = 0;

    // front-batched loads: sidx coalesced, entry gather (L2-resident table)
    int sidx[IPT];
    unsigned long long cell[IPT];
    #pragma unroll
    for (int k = 0; k < IPT; k++) {
        int i = base + k * BLK + tid;
        sidx[k] = (i < n) ? g_sidx[i] : -1;
    }
    #pragma unroll
    for (int k = 0; k < IPT; k++)
        cell[k] = (sidx[k] >= 0) ? __ldcg(&g_htab[sidx[k]]) : 0ull;

    int flat[IPT], key[IPT];
    #pragma unroll
    for (int k = 0; k < IPT; k++) {
        flat[k] = (int)(cell[k] >> 21) - 1;        // -1 when invalid (cell==0)
        key[k] = (int)(cell[k] & 0x1FFFFFull);     // n - i_rep
    }
    __syncthreads();

    // per-slice block scan of rep flags (slices in point-index order)
    int rep[IPT], localPos[IPT];
    #pragma unroll
    for (int k = 0; k < IPT; k++) {
        int i = base + k * BLK + tid;
        int r = (sidx[k] >= 0 && key[k] == n - i) ? 1 : 0;
        rep[k] = r;
        unsigned m = __ballot_sync(0xffffffffu, r);
        int lanePre = __popc(m & ((1u << lane) - 1u));
        if (lane == 0) s_warp[wid] = __popc(m);
        __syncthreads();
        if (tid == 0) {
            int acc = s_run;
            #pragma unroll
            for (int w = 0; w < BLK / 32; w++) { int t = s_warp[w]; s_wexcl[w] = acc; acc += t; }
            s_run = acc;
        }
        __syncthreads();
        localPos[k] = s_wexcl[wid] + lanePre;
    }
    int agg = s_run;

    // publish aggregate, warp-parallel lookback (volatile — proven R4-R6)
    volatile unsigned* vst = g_status;
    if (wid == 0) {
        if (lane == 0) vst[tile] = 0x40000000u | (unsigned)agg;
        unsigned excl = 0;
        int j = tile - 1;
        while (j >= 0) {
            int idx = j - lane;
            unsigned w;
            if (idx >= 0) {
                do { w = vst[idx]; } while (w == 0u);
            } else {
                w = 0x80000000u;  // virtual prefix 0 before tile 0
            }
            unsigned isPre = __ballot_sync(0xffffffffu, (w & 0x80000000u) != 0u);
            if (isPre) {
                int pl = __ffs(isPre) - 1;
                unsigned contrib = (lane <= pl) ? (w & 0x3FFFFFFFu) : 0u;
                #pragma unroll
                for (int o = 16; o; o >>= 1) contrib += __shfl_down_sync(0xffffffffu, contrib, o);
                if (lane == 0) excl += contrib;
                break;
            } else {
                unsigned contrib = w & 0x3FFFFFFFu;
                #pragma unroll
                for (int o = 16; o; o >>= 1) contrib += __shfl_down_sync(0xffffffffu, contrib, o);
                if (lane == 0) excl += contrib;
                j -= 32;
            }
        }
        if (lane == 0) {
            s_excl = (int)excl;
            vst[tile] = 0x80000000u | (excl + (unsigned)agg);
            if (tile == nTiles - 1) {
                int tot = (int)(excl + (unsigned)agg);
                g_voxelNum = tot < MAXV ? tot : MAXV;
            }
        }
    }
    __syncthreads();
    int excl = s_excl;

    // phase 3: reps emit everything; non-reps get compacted (no divergent breaks)
    #pragma unroll
    for (int k = 0; k < IPT; k++) {
        int i = base + k * BLK + tid;
        bool valid = (i < n) && (sidx[k] >= 0);
        bool isRep = valid && rep[k];
        if (isRep) {
            int vid = excl + localPos[k];
            g_pvid[i] = PV_RESOLVED | vid;
            if (vid < MAXV) {
                int f = flat[k];
                g_coors[vid * 3 + 0] = f % GZ;
                g_coors[vid * 3 + 1] = (f / GZ) % GY;
                g_coors[vid * 3 + 2] = f / (GZ * GY);
                // one rep per voxel: uncontended plain stores (kC runs later)
                g_slots[vid * MAXP] = (unsigned)(n - i);
                g_cnt[vid] = 1;
            }
        }
        bool isNR = valid && !rep[k];
        unsigned m = __ballot_sync(0xffffffffu, isNR);
        if (m) {
            int pre = __popc(m & ((1u << lane) - 1u));
            int wb;
            if (lane == 0) wb = atomicAdd(&g_nrCount, __popc(m));
            wb = __shfl_sync(0xffffffffu, wb, 0);
            if (isNR)
                g_nrList[wb + pre] =
                    ((unsigned long long)(unsigned)i << 21) | (unsigned)(n - key[k]);
        }
    }
}

// ---------------------------------------------------------------------------
// C: micro-kernel over the ~1% non-rep points. Lookup rep's vid; count +
// deterministic atomicMax ripple (final = 32 smallest indices, sorted).
// ---------------------------------------------------------------------------
__global__ void kC_nonrep(int n) {
    int total = g_nrCount;
    for (int j = blockIdx.x * blockDim.x + threadIdx.x; j < total;
         j += gridDim.x * blockDim.x) {
        unsigned long long e = g_nrList[j];
        int i = (int)(e >> 21);
        int irep = (int)(e & 0x1FFFFFull);
        int vid = __ldcg(&g_pvid[irep]) & (PV_RESOLVED - 1);
        if (vid >= MAXV) continue;
        atomicAdd(&g_cnt[vid], 1);
        unsigned key = (unsigned)(n - i);
        unsigned* sl = &g_slots[(unsigned)vid * MAXP];
        for (int s = 0; s < MAXP; s++) {
            unsigned old = atomicMax(&sl[s], key);
            if (old < key) {
                if (old == 0u) break;  // landed in empty slot
                key = old;             // displaced occupant ripples right
            }
        }
    }
}

// ---------------------------------------------------------------------------
// D: emit outputs (4 slots/thread, conditional slot reset), stream-zero hash
// table, clear status + nrCount.
// Output layout: voxels[60000*32*4] | coors[60000*3] | npv[60000] | voxel_num[1]
// ---------------------------------------------------------------------------
__global__ void kD_emit(const float4* __restrict__ pts, float* __restrict__ out,
                        int n, int nTiles) {
    const int NSL4 = SLOTS / 4;
    int idx = blockIdx.x * BLK + threadIdx.x;
    if (idx < NSL4) {
        int base = idx * 4;
        uint4 kk = reinterpret_cast<const uint4*>(g_slots)[idx];
        if (kk.x | kk.y | kk.z | kk.w)
            reinterpret_cast<uint4*>(g_slots)[idx] = make_uint4(0u, 0u, 0u, 0u);
        float4 v0 = make_float4(0.f, 0.f, 0.f, 0.f), v1 = v0, v2 = v0, v3 = v0;
        if (kk.x) v0 = pts[n - (int)kk.x];
        if (kk.y) v1 = pts[n - (int)kk.y];
        if (kk.z) v2 = pts[n - (int)kk.z];
        if (kk.w) v3 = pts[n - (int)kk.w];
        float4* o = reinterpret_cast<float4*>(out) + base;
        o[0] = v0; o[1] = v1; o[2] = v2; o[3] = v3;
        if ((base & 31) == 0) {
            int vid = base >> 5;
            int c = g_cnt[vid];
            if (c) g_cnt[vid] = 0;
            if (c > MAXP) c = MAXP;
            const int OC = SLOTS * 4;
            const int ON = OC + MAXV * 3;
            out[ON + vid] = (float)c;
            int vn = g_voxelNum;
            float cz = 0.f, cy = 0.f, cx = 0.f;
            if (vid < vn) {
                cz = (float)g_coors[vid * 3 + 0];
                cy = (float)g_coors[vid * 3 + 1];
                cx = (float)g_coors[vid * 3 + 2];
            }
            out[OC + vid * 3 + 0] = cz;
            out[OC + vid * 3 + 1] = cy;
            out[OC + vid * 3 + 2] = cx;
            if (idx == 0) out[ON + MAXV] = (float)vn;
        }
    } else {
        int j = idx - NSL4;
        if (j < (int)(HSIZE / 2)) {
            reinterpret_cast<ulonglong2*>(g_htab)[j] = make_ulonglong2(0ull, 0ull);
        } else {
            int j2 = j - (int)(HSIZE / 2);
            if (j2 < nTiles) g_status[j2] = 0;
            if (j2 == nTiles) g_nrCount = 0;
        }
    }
}

extern "C" void kernel_launch(void* const* d_in, const int* in_sizes, int n_in,
                              void* d_out, int out_size) {
    const float4* pts = (const float4*)d_in[0];
    int n = in_sizes[0] / 4;
    float* out = (float*)d_out;
    int nT = (n + TILE - 1) / TILE;

    kA_claim<<<nT, BLK>>>(pts, n);
    kB_scan_assign<<<nT, BLK>>>(n, nT);
    kC_nonrep<<<96, BLK>>>(n);
    kD_emit<<<(SLOTS / 4 + (int)(HSIZE / 2) + nT + 1 + BLK - 1) / BLK, BLK>>>(pts, out, n, nT);
}

// round 8
// speedup vs baseline: 1.2649x; 1.2649x over previous
#include <cuda_runtime.h>

#define GX 1024
#define GY 1024
#define GZ 40
#define MAXV 60000
#define MAXP 32
#define SLOTS (MAXV * MAXP)
#define BLK 256
#define IPT 4
#define TILE (BLK * IPT)
#define NMAX 1250000
#define NTMAX ((NMAX + TILE - 1) / TILE + 8)
#define PV_RESOLVED 0x40000000
#define NRB 32  // non-rep blocks in kC

// L2-resident open-addressing hash table. Entry: 0 = empty,
// else ((flat+1) << 21) | key, key = n - i (n < 2^21). Cell ownership is
// set-once (CAS from 0); all same-flat contenders then share high bits so
// atomicMax == per-voxel first-point claim. Each flat resolves to exactly one
// slot (set-once ownership makes every same-flat probe walk stop at the same
// cell). Zeroed in kC each call.
#define HBITS 21
#define HSIZE (1u << HBITS)
#define HMASK (HSIZE - 1u)
#define KMASK 0x1FFFFFull

__device__ __align__(16) unsigned long long g_htab[HSIZE];
__device__ int      g_sidx[NMAX];     // resolved hash slot per point, -1 invalid
__device__ int      g_pvid[NMAX];     // reps: PV_RESOLVED|vid (others stale, never read)
__device__ unsigned long long g_nrList[NMAX];  // non-reps: (i << 21) | i_rep
__device__ int      g_nrCount;        // reset by kD
__device__ unsigned g_status[NTMAX];  // lookback: 0 | 0x4000_0000|agg | 0x8000_0000|incl
__device__ int      g_voxelNum;
__device__ unsigned g_slots[SLOTS];   // keys; only voxels with cnt>=1 touched; reset by kD
__device__ int      g_cnt[MAXV];      // reset by kD
__device__ int      g_coors[MAXV * 3];

__device__ __forceinline__ unsigned hslot(int flat) {
    return (unsigned)(((unsigned long long)(unsigned)flat * 0x9E3779B97F4A7C15ull) >> (64 - HBITS));
}

// ---------------------------------------------------------------------------
// A: 4 consecutive points per thread; coords -> CAS-first hash claim; cache
// resolved slot index (int4 store).
// ---------------------------------------------------------------------------
__global__ void kA_claim(const float4* __restrict__ pts, int n) {
    int t = blockIdx.x * BLK + threadIdx.x;
    int i0 = t * IPT;
    int sres[IPT];
    #pragma unroll
    for (int k = 0; k < IPT; k++) {
        int i = i0 + k;
        int sidx = -1;
        if (i < n) {
            float4 p = pts[i];
            // exact mirror of reference f32 math: floor((p - rmin) / vs)
            int cx = (int)floorf((p.x - (-51.2f)) / 0.1f);
            int cy = (int)floorf((p.y - (-51.2f)) / 0.1f);
            int cz = (int)floorf((p.z - (-5.0f)) / 0.2f);
            if ((unsigned)cx < GX && (unsigned)cy < GY && (unsigned)cz < GZ) {
                int flat = (cx * GY + cy) * GZ + cz;
                unsigned long long fp1 = (unsigned long long)(unsigned)(flat + 1);
                unsigned key = (unsigned)(n - i);
                unsigned long long ent = (fp1 << 21) | key;
                unsigned s = hslot(flat);
                for (;;) {
                    unsigned long long old = atomicCAS(&g_htab[s], 0ull, ent);
                    if (old == 0ull) break;                       // claimed empty slot
                    if ((old >> 21) == fp1) {                     // our voxel's slot
                        if ((unsigned)(old & KMASK) < key) atomicMax(&g_htab[s], ent);
                        break;
                    }
                    s = (s + 1) & HMASK;                          // other flat: probe on
                }
                sidx = (int)s;
            }
        }
        sres[k] = sidx;
    }
    if (i0 + IPT <= n) {
        *reinterpret_cast<int4*>(&g_sidx[i0]) = make_int4(sres[0], sres[1], sres[2], sres[3]);
    } else {
        for (int k = 0; k < IPT; k++)
            if (i0 + k < n) g_sidx[i0 + k] = sres[k];
    }
}

// ---------------------------------------------------------------------------
// B: entry gather -> rep flags -> single block scan + decoupled lookback ->
// vid. Reps write pvid, and (vid<MAXV) coors + slot0 key + cnt=1 + the OUTPUT
// row directly (slot 0 is always the rep: ripple keys are descending).
// Non-reps (~0.5%) warp-aggregate into a compact list.
// ---------------------------------------------------------------------------
__global__ void kB_scan_assign(const float4* __restrict__ pts, float* __restrict__ out,
                               int n, int nTiles) {
    const int tid = threadIdx.x;
    const int lane = tid & 31, wid = tid >> 5;
    const int tile = blockIdx.x;
    const int i0 = (tile * BLK + tid) * IPT;

    __shared__ int s_warp[BLK / 32];
    __shared__ int s_incl[BLK / 32];
    __shared__ int s_run;
    __shared__ int s_excl;

    // front-batched loads: sidx (int4), entry gathers (L2-resident table)
    int sidx[IPT];
    if (i0 + IPT <= n) {
        int4 s4 = *reinterpret_cast<const int4*>(&g_sidx[i0]);
        sidx[0] = s4.x; sidx[1] = s4.y; sidx[2] = s4.z; sidx[3] = s4.w;
    } else {
        #pragma unroll
        for (int k = 0; k < IPT; k++)
            sidx[k] = (i0 + k < n) ? g_sidx[i0 + k] : -1;
    }
    unsigned long long cell[IPT];
    #pragma unroll
    for (int k = 0; k < IPT; k++)
        cell[k] = (sidx[k] >= 0) ? __ldcg(&g_htab[sidx[k]]) : 0ull;

    int flat[IPT], key[IPT], rep[IPT];
    int c = 0;
    #pragma unroll
    for (int k = 0; k < IPT; k++) {
        flat[k] = (int)(cell[k] >> 21) - 1;
        key[k] = (int)(cell[k] & KMASK);          // n - i_rep
        rep[k] = (sidx[k] >= 0 && key[k] == n - (i0 + k)) ? 1 : 0;
        c += rep[k];
    }

    // single block exclusive scan of per-thread counts (point order == tid,k order)
    int v = c;
    #pragma unroll
    for (int o = 1; o < 32; o <<= 1) {
        int tv = __shfl_up_sync(0xffffffffu, v, o);
        if (lane >= o) v += tv;
    }
    if (lane == 31) s_warp[wid] = v;
    __syncthreads();
    if (tid < BLK / 32) {
        int w = s_warp[tid];
        #pragma unroll
        for (int o = 1; o < BLK / 32; o <<= 1) {
            int tv = __shfl_up_sync(0xffu, w, o);
            if (tid >= o) w += tv;
        }
        s_incl[tid] = w;
        if (tid == BLK / 32 - 1) s_run = w;
    }
    __syncthreads();
    int thrExcl = (wid ? s_incl[wid - 1] : 0) + (v - c);
    int agg = s_run;

    // publish aggregate, warp-parallel lookback (volatile — proven R4-R7)
    volatile unsigned* vst = g_status;
    if (wid == 0) {
        if (lane == 0) vst[tile] = 0x40000000u | (unsigned)agg;
        unsigned excl = 0;
        int j = tile - 1;
        while (j >= 0) {
            int idx = j - lane;
            unsigned w;
            if (idx >= 0) {
                do { w = vst[idx]; } while (w == 0u);
            } else {
                w = 0x80000000u;  // virtual prefix 0 before tile 0
            }
            unsigned isPre = __ballot_sync(0xffffffffu, (w & 0x80000000u) != 0u);
            if (isPre) {
                int pl = __ffs(isPre) - 1;
                unsigned contrib = (lane <= pl) ? (w & 0x3FFFFFFFu) : 0u;
                #pragma unroll
                for (int o = 16; o; o >>= 1) contrib += __shfl_down_sync(0xffffffffu, contrib, o);
                if (lane == 0) excl += contrib;
                break;
            } else {
                unsigned contrib = w & 0x3FFFFFFFu;
                #pragma unroll
                for (int o = 16; o; o >>= 1) contrib += __shfl_down_sync(0xffffffffu, contrib, o);
                if (lane == 0) excl += contrib;
                j -= 32;
            }
        }
        if (lane == 0) {
            s_excl = (int)excl;
            vst[tile] = 0x80000000u | (excl + (unsigned)agg);
            if (tile == nTiles - 1) {
                int tot = (int)(excl + (unsigned)agg);
                g_voxelNum = tot < MAXV ? tot : MAXV;
            }
        }
    }
    __syncthreads();
    int base = s_excl + thrExcl;

    // phase 3: reps emit (incl. the output row); non-reps compacted
    int running = 0;
    #pragma unroll
    for (int k = 0; k < IPT; k++) {
        int i = i0 + k;
        bool valid = (i < n) && (sidx[k] >= 0);
        bool isRep = valid && rep[k];
        if (isRep) {
            int vid = base + running;
            running++;
            g_pvid[i] = PV_RESOLVED | vid;
            if (vid < MAXV) {
                int f = flat[k];
                g_coors[vid * 3 + 0] = f % GZ;
                g_coors[vid * 3 + 1] = (f / GZ) % GY;
                g_coors[vid * 3 + 2] = f / (GZ * GY);
                g_slots[vid * MAXP] = (unsigned)(n - i);  // rep key guards slot 0
                g_cnt[vid] = 1;
                reinterpret_cast<float4*>(out)[vid * MAXP] = pts[i];  // slot 0 = rep, final
            }
        }
        bool isNR = valid && !rep[k];
        unsigned m = __ballot_sync(0xffffffffu, isNR);
        if (m) {
            int pre = __popc(m & ((1u << lane) - 1u));
            int wb;
            if (lane == 0) wb = atomicAdd(&g_nrCount, __popc(m));
            wb = __shfl_sync(0xffffffffu, wb, 0);
            if (isNR)
                g_nrList[wb + pre] =
                    ((unsigned long long)(unsigned)i << 21) | (unsigned)(n - key[k]);
        }
    }
}

// ---------------------------------------------------------------------------
// C: split grid — first NRB blocks: non-rep inserts (rep vid lookup + count +
// deterministic atomicMax ripple; rep key in slot 0 pushes them to slot 1+).
// Remaining blocks: stream-zero the hash table + clear lookback status,
// overlapped with the ripples inside one launch.
// ---------------------------------------------------------------------------
__global__ void kC_nonrep_clean(int n, int nTiles) {
    int b = blockIdx.x;
    if (b < NRB) {
        int total = g_nrCount;
        for (int j = b * BLK + threadIdx.x; j < total; j += NRB * BLK) {
            unsigned long long e = g_nrList[j];
            int i = (int)(e >> 21);
            int irep = (int)(e & KMASK);
            int vid = __ldcg(&g_pvid[irep]) & (PV_RESOLVED - 1);
            if (vid >= MAXV) continue;
            atomicAdd(&g_cnt[vid], 1);
            unsigned key = (unsigned)(n - i);
            unsigned* sl = &g_slots[(unsigned)vid * MAXP];
            for (int s = 0; s < MAXP; s++) {
                unsigned old = atomicMax(&sl[s], key);
                if (old < key) {
                    if (old == 0u) break;  // landed in empty slot
                    key = old;             // displaced occupant ripples right
                }
            }
        }
    } else {
        int j = (b - NRB) * BLK + threadIdx.x;
        if (j < (int)(HSIZE / 2)) {
            reinterpret_cast<ulonglong2*>(g_htab)[j] = make_ulonglong2(0ull, 0ull);
        } else {
            int j2 = j - (int)(HSIZE / 2);
            if (j2 < nTiles) g_status[j2] = 0;
        }
    }
}

// ---------------------------------------------------------------------------
// D: warp-per-voxel emit. cnt==1 (vast majority): 31 zero rows, reset slot 0,
// no slot reads. cnt>1 (rare): read keys, gather points. cnt==0: full zero.
// Slot 0's output row was already written by kB. Also npv/coors/voxel_num +
// cnt/nrCount reset.
// Output layout: voxels[60000*32*4] | coors[60000*3] | npv[60000] | voxel_num[1]
// ---------------------------------------------------------------------------
__global__ void kD_emit(const float4* __restrict__ pts, float* __restrict__ out, int n) {
    int idx = blockIdx.x * BLK + threadIdx.x;   // [0, SLOTS)
    int vid = idx >> 5, lane = idx & 31;
    int c = 0;
    if (lane == 0) c = g_cnt[vid];
    c = __shfl_sync(0xffffffffu, c, 0);

    const float4 zero = make_float4(0.f, 0.f, 0.f, 0.f);
    if (c == 0) {
        reinterpret_cast<float4*>(out)[idx] = zero;
    } else if (c == 1) {
        if (lane) reinterpret_cast<float4*>(out)[idx] = zero;
        else g_slots[idx] = 0;  // reset rep key; out row 0 written by kB
    } else {
        unsigned k = g_slots[idx];
        g_slots[idx] = 0;
        if (lane)  // lane 0's row written by kB (slot 0 == rep, final)
            reinterpret_cast<float4*>(out)[idx] = k ? pts[n - (int)k] : zero;
    }
    if (lane == 0) {
        if (c) g_cnt[vid] = 0;
        int npv = c > MAXP ? MAXP : c;
        const int OC = SLOTS * 4;
        const int ON = OC + MAXV * 3;
        out[ON + vid] = (float)npv;
        int vn = g_voxelNum;
        float cz = 0.f, cy = 0.f, cx = 0.f;
        if (vid < vn) {
            cz = (float)g_coors[vid * 3 + 0];
            cy = (float)g_coors[vid * 3 + 1];
            cx = (float)g_coors[vid * 3 + 2];
        }
        out[OC + vid * 3 + 0] = cz;
        out[OC + vid * 3 + 1] = cy;
        out[OC + vid * 3 + 2] = cx;
        if (idx == 0) {
            out[ON + MAXV] = (float)vn;
            g_nrCount = 0;
        }
    }
}

extern "C" void kernel_launch(void* const* d_in, const int* in_sizes, int n_in,
                              void* d_out, int out_size) {
    const float4* pts = (const float4*)d_in[0];
    int n = in_sizes[0] / 4;
    float* out = (float*)d_out;
    int nT = (n + TILE - 1) / TILE;

    kA_claim<<<nT, BLK>>>(pts, n);
    kB_scan_assign<<<nT, BLK>>>(pts, out, n, nT);
    int zBlocks = ((int)(HSIZE / 2) + nT + BLK - 1) / BLK;
    kC_nonrep_clean<<<NRB + zBlocks, BLK>>>(n, nT);
    kD_emit<<<SLOTS / BLK, BLK>>>(pts, out, n);
}